// round 7
// baseline (speedup 1.0000x reference)
#include <cuda_runtime.h>
#include <cuda_fp16.h>
#include <math.h>
#include <stdint.h>

constexpr int B_ = 8, T_ = 2048, E_ = 1024, D_ = 64;
constexpr int BT_ = B_ * T_;
constexpr int NC_ = 192;   // concatenated q|k|v columns

// Split-fp16 Q,K,V (proj output; q pre-scaled by 0.125) and W [1024,192].
__device__ __half g_hi[BT_ * NC_];
__device__ __half g_lo[BT_ * NC_];
__device__ __half g_whi[E_ * NC_];
__device__ __half g_wlo[E_ * NC_];

// ---------------------------------------------------------------------------
// Helpers
// ---------------------------------------------------------------------------
__device__ __forceinline__ uint32_t su32(const void* p) {
    return (uint32_t)__cvta_generic_to_shared(p);
}
__device__ __forceinline__ void ldsm_x4(uint32_t* r, uint32_t a) {
    asm volatile("ldmatrix.sync.aligned.m8n8.x4.shared.b16 {%0,%1,%2,%3}, [%4];"
                 : "=r"(r[0]), "=r"(r[1]), "=r"(r[2]), "=r"(r[3]) : "r"(a));
}
__device__ __forceinline__ void ldsm_x4t(uint32_t* r, uint32_t a) {
    asm volatile("ldmatrix.sync.aligned.m8n8.x4.trans.shared.b16 {%0,%1,%2,%3}, [%4];"
                 : "=r"(r[0]), "=r"(r[1]), "=r"(r[2]), "=r"(r[3]) : "r"(a));
}
__device__ __forceinline__ void mma16816(float* c, const uint32_t* a, const uint32_t* b) {
    asm volatile("mma.sync.aligned.m16n8k16.row.col.f32.f16.f16.f32 "
                 "{%0,%1,%2,%3},{%4,%5,%6,%7},{%8,%9},{%0,%1,%2,%3};"
                 : "+f"(c[0]), "+f"(c[1]), "+f"(c[2]), "+f"(c[3])
                 : "r"(a[0]), "r"(a[1]), "r"(a[2]), "r"(a[3]), "r"(b[0]), "r"(b[1]));
}
__device__ __forceinline__ void split2(float a, float b, uint32_t& hi, uint32_t& lo) {
    __half ha = __float2half_rn(a), hb = __float2half_rn(b);
    __half2 H = __halves2half2(ha, hb);
    hi = *reinterpret_cast<uint32_t*>(&H);
    __half2 L = __halves2half2(__float2half_rn(a - __half2float(ha)),
                               __float2half_rn(b - __half2float(hb)));
    lo = *reinterpret_cast<uint32_t*>(&L);
}
__device__ __forceinline__ void cp16(void* dst, const void* src) {
    asm volatile("cp.async.cg.shared.global [%0], [%1], 16;"
                 :: "r"(su32(dst)), "l"(src) : "memory");
}
__device__ __forceinline__ void cp_commit() {
    asm volatile("cp.async.commit_group;" ::: "memory");
}
template <int N> __device__ __forceinline__ void cp_wait() {
    asm volatile("cp.async.wait_group %0;" :: "n"(N) : "memory");
}

// ---------------------------------------------------------------------------
// W prepack: [1024 x 192] split halves.
// ---------------------------------------------------------------------------
__global__ void wprep_kernel(const float* __restrict__ Wq,
                             const float* __restrict__ Wk,
                             const float* __restrict__ Wv) {
    int idx = blockIdx.x * 256 + threadIdx.x;
    if (idx >= E_ * NC_) return;
    int k = idx / NC_, c = idx % NC_;
    float w = (c < 64) ? Wq[k * 64 + c] : (c < 128) ? Wk[k * 64 + c - 64]
                                                    : Wv[k * 64 + c - 128];
    __half h = __float2half_rn(w);
    g_whi[idx] = h;
    g_wlo[idx] = __float2half_rn(w - __half2float(h));
}

// ---------------------------------------------------------------------------
// Fused QKV projection, HMMA split-fp16, double-buffered.
// BM=64, BN=192, BK=32, 8 warps (4m x 2n), warp tile 16x96.
// x prefetched via registers; W streamed via cp.async (2 stages).
// Epilogue: bias add, q-columns pre-scaled by 0.125, split-halves store.
// ---------------------------------------------------------------------------
constexpr int XS_ = 40;    // xs row stride (halves)
constexpr int WS_ = 200;   // ws row stride (halves)
constexpr int PXS = 64 * XS_;          // 2560 halves per x buffer
constexpr int PWS = 32 * WS_;          // 6400 halves per w buffer
constexpr int PSTG = 2 * PXS + 2 * PWS; // halves per stage (17920)
constexpr int PROJ_SMEM = 2 * PSTG * 2; // bytes (71680)

__global__ __launch_bounds__(256) void qkv_proj_kernel(
    const float* __restrict__ x,
    const float* __restrict__ bq, const float* __restrict__ bk,
    const float* __restrict__ bv)
{
    extern __shared__ __align__(16) __half Ps[];

    const int tid = threadIdx.x, wid = tid >> 5, lane = tid & 31;
    const int gid = lane >> 2, tig = lane & 3;
    const int m0 = blockIdx.x * 64;
    const int wm = (wid >> 1) * 16, wn = (wid & 1) * 96;

    float acc[12][4];
    #pragma unroll
    for (int j = 0; j < 12; j++)
        #pragma unroll
        for (int c = 0; c < 4; c++) acc[j][c] = 0.0f;

    const int xr = tid >> 3, xcg = tid & 7;             // x load coords (2/thread)
    const int wr0 = tid / 24, wc0 = tid % 24;           // w load coords (3/thread)

    // Prologue: x chunk 0 into regs, W chunk 0 into stage 0 via cp.async.
    float4 xv[2];
    #pragma unroll
    for (int i = 0; i < 2; i++) {
        int lin = tid + i * 256;
        xv[i] = *(const float4*)&x[(size_t)(m0 + (lin >> 3)) * E_ + (lin & 7) * 4];
    }
    {
        __half* wh = Ps + 2 * PXS;
        __half* wl = wh + PWS;
        #pragma unroll
        for (int i = 0; i < 3; i++) {
            int lin = tid + i * 256;
            int r = lin / 24, cg = lin % 24;
            cp16(&wh[r * WS_ + cg * 8], &g_whi[(size_t)r * NC_ + cg * 8]);
            cp16(&wl[r * WS_ + cg * 8], &g_wlo[(size_t)r * NC_ + cg * 8]);
        }
        cp_commit();
    }

    for (int c = 0; c < E_ / 32; c++) {
        const int p = c & 1;
        __half* xh = Ps + p * PSTG;
        __half* xl = xh + PXS;
        __half* wh = xl + PXS;
        __half* wl = wh + PWS;

        // Store prefetched x regs (split) into stage p.
        #pragma unroll
        for (int i = 0; i < 2; i++) {
            int lin = tid + i * 256;
            int r = lin >> 3, cg = lin & 7;
            uint32_t h0, l0, h1, l1;
            split2(xv[i].x, xv[i].y, h0, l0);
            split2(xv[i].z, xv[i].w, h1, l1);
            *(uint32_t*)&xh[r * XS_ + cg * 4]     = h0;
            *(uint32_t*)&xh[r * XS_ + cg * 4 + 2] = h1;
            *(uint32_t*)&xl[r * XS_ + cg * 4]     = l0;
            *(uint32_t*)&xl[r * XS_ + cg * 4 + 2] = l1;
        }

        if (c + 1 < E_ / 32) {
            const int k1 = (c + 1) * 32;
            #pragma unroll
            for (int i = 0; i < 2; i++) {
                int lin = tid + i * 256;
                xv[i] = *(const float4*)&x[(size_t)(m0 + (lin >> 3)) * E_ + k1 + (lin & 7) * 4];
            }
            __half* nwh = Ps + (p ^ 1) * PSTG + 2 * PXS;
            __half* nwl = nwh + PWS;
            #pragma unroll
            for (int i = 0; i < 3; i++) {
                int lin = tid + i * 256;
                int r = lin / 24, cg = lin % 24;
                cp16(&nwh[r * WS_ + cg * 8], &g_whi[(size_t)(k1 + r) * NC_ + cg * 8]);
                cp16(&nwl[r * WS_ + cg * 8], &g_wlo[(size_t)(k1 + r) * NC_ + cg * 8]);
            }
            cp_commit();
            cp_wait<1>();
        } else {
            cp_wait<0>();
        }
        __syncthreads();

        #pragma unroll
        for (int kc = 0; kc < 2; kc++) {
            uint32_t ah[4], al[4];
            int arow = wm + (lane & 15);
            int acol = kc * 16 + (lane >> 4) * 8;
            ldsm_x4(ah, su32(&xh[arow * XS_ + acol]));
            ldsm_x4(al, su32(&xl[arow * XS_ + acol]));
            #pragma unroll
            for (int j = 0; j < 12; j += 2) {
                uint32_t bh[4], bl[4];
                int brow = kc * 16 + (lane & 15);
                int bcol = wn + 8 * j + (lane >> 4) * 8;
                ldsm_x4t(bh, su32(&wh[brow * WS_ + bcol]));
                ldsm_x4t(bl, su32(&wl[brow * WS_ + bcol]));
                mma16816(acc[j],     ah, bh);
                mma16816(acc[j],     ah, bl);
                mma16816(acc[j],     al, bh);
                mma16816(acc[j + 1], ah, bh + 2);
                mma16816(acc[j + 1], ah, bl + 2);
                mma16816(acc[j + 1], al, bh + 2);
            }
        }
        __syncthreads();
    }

    // Epilogue: bias, q pre-scale (exact pow2), split, store.
    const int r0 = m0 + wm + gid;
    #pragma unroll
    for (int j = 0; j < 12; j++) {
        int col = wn + 8 * j + 2 * tig;
        const float* bias = (col < 64) ? bq : (col < 128) ? bk : bv;
        float sc = (col < 64) ? 0.125f : 1.0f;
        int bc = col & 63;
        float b0 = bias[bc], b1 = bias[bc + 1];
        uint32_t hi, lo;
        split2((acc[j][0] + b0) * sc, (acc[j][1] + b1) * sc, hi, lo);
        *(uint32_t*)&g_hi[(size_t)r0 * NC_ + col] = hi;
        *(uint32_t*)&g_lo[(size_t)r0 * NC_ + col] = lo;
        split2((acc[j][2] + b0) * sc, (acc[j][3] + b1) * sc, hi, lo);
        *(uint32_t*)&g_hi[(size_t)(r0 + 8) * NC_ + col] = hi;
        *(uint32_t*)&g_lo[(size_t)(r0 + 8) * NC_ + col] = lo;
    }
}

// ---------------------------------------------------------------------------
// Flash attention on HMMA, double-buffered K/V via cp.async.
// Br=64, Bc=64, 4 warps; Q pre-scaled so S needs no scale multiply.
// ---------------------------------------------------------------------------
constexpr int KS_ = 72;                 // smem row stride (halves)
constexpr int ATS = 64 * KS_;           // halves per K/V buffer (4608)
constexpr int ASTG = 4 * ATS;           // halves per stage (Kh,Kl,Vh,Vl)
constexpr int ATTN_SMEM = 2 * ASTG * 2; // bytes (73728)

__global__ __launch_bounds__(128) void flash_attn_kernel(float* __restrict__ out)
{
    extern __shared__ __align__(16) __half As[];

    const int tid = threadIdx.x, wid = tid >> 5, lane = tid & 31;
    const int gid = lane >> 2, tig = lane & 3;
    const int b = blockIdx.y;
    const int qt = (T_ / 64 - 1) - blockIdx.x;   // heavy tiles first
    const int m0 = qt * 64;
    const int rowbase = b * T_;

    // Issue K/V loads for one tile into a stage.
    auto issue_tile = [&](int nt, int st) {
        __half* Kh = As + st * ASTG;
        __half* Kl = Kh + ATS;
        __half* Vh = Kl + ATS;
        __half* Vl = Vh + ATS;
        const int n0 = nt * 64;
        #pragma unroll
        for (int i = 0; i < 4; i++) {
            int lin = tid + i * 128;
            int r = lin >> 3, cg = lin & 7;
            const size_t g = (size_t)(rowbase + n0 + r) * NC_;
            cp16(&Kh[r * KS_ + cg * 8], &g_hi[g + 64 + cg * 8]);
            cp16(&Kl[r * KS_ + cg * 8], &g_lo[g + 64 + cg * 8]);
            cp16(&Vh[r * KS_ + cg * 8], &g_hi[g + 128 + cg * 8]);
            cp16(&Vl[r * KS_ + cg * 8], &g_lo[g + 128 + cg * 8]);
        }
        cp_commit();
    };

    issue_tile(0, 0);

    // Q fragments from global (hi and lo), 4 k-chunks of 16. Pre-scaled.
    uint32_t qh[4][4], ql[4][4];
    {
        const size_t r0 = (size_t)(rowbase + m0 + wid * 16 + gid) * NC_;
        #pragma unroll
        for (int kc = 0; kc < 4; kc++) {
            int c0 = kc * 16 + 2 * tig;
            qh[kc][0] = *(const uint32_t*)&g_hi[r0 + c0];
            qh[kc][1] = *(const uint32_t*)&g_hi[r0 + 8 * NC_ + c0];
            qh[kc][2] = *(const uint32_t*)&g_hi[r0 + c0 + 8];
            qh[kc][3] = *(const uint32_t*)&g_hi[r0 + 8 * NC_ + c0 + 8];
            ql[kc][0] = *(const uint32_t*)&g_lo[r0 + c0];
            ql[kc][1] = *(const uint32_t*)&g_lo[r0 + 8 * NC_ + c0];
            ql[kc][2] = *(const uint32_t*)&g_lo[r0 + c0 + 8];
            ql[kc][3] = *(const uint32_t*)&g_lo[r0 + 8 * NC_ + c0 + 8];
        }
    }

    float o[8][4];
    #pragma unroll
    for (int j = 0; j < 8; j++)
        #pragma unroll
        for (int c = 0; c < 4; c++) o[j][c] = 0.0f;
    float mrow0 = -INFINITY, mrow1 = -INFINITY, lrow0 = 0.0f, lrow1 = 0.0f;

    for (int nt = 0; nt <= qt; nt++) {
        const int n0 = nt * 64;
        const int p = nt & 1;
        __half* Kh = As + p * ASTG;
        __half* Kl = Kh + ATS;
        __half* Vh = Kl + ATS;
        __half* Vl = Vh + ATS;

        if (nt < qt) { issue_tile(nt + 1, p ^ 1); cp_wait<1>(); }
        else         { cp_wait<0>(); }
        __syncthreads();

        // S = Q K^T (split-fp16, 3 mma per logical). Q carries the 1/8 scale.
        float s[8][4];
        #pragma unroll
        for (int j = 0; j < 8; j++)
            #pragma unroll
            for (int c = 0; c < 4; c++) s[j][c] = 0.0f;

        #pragma unroll
        for (int kc = 0; kc < 4; kc++) {
            #pragma unroll
            for (int j = 0; j < 8; j += 2) {
                int key = 8 * j + (lane >> 4) * 8 + (lane & 7);
                int c   = kc * 16 + ((lane >> 3) & 1) * 8;
                uint32_t kh[4], kl[4];
                ldsm_x4(kh, su32(&Kh[key * KS_ + c]));
                ldsm_x4(kl, su32(&Kl[key * KS_ + c]));
                mma16816(s[j],     qh[kc], kh);
                mma16816(s[j],     qh[kc], kl);
                mma16816(s[j],     ql[kc], kh);
                mma16816(s[j + 1], qh[kc], kh + 2);
                mma16816(s[j + 1], qh[kc], kl + 2);
                mma16816(s[j + 1], ql[kc], kh + 2);
            }
        }

        // Causal mask (diagonal tile only; scale already folded into Q).
        if (nt == qt) {
            int r0 = m0 + wid * 16 + gid;
            #pragma unroll
            for (int j = 0; j < 8; j++) {
                int c0 = n0 + 8 * j + 2 * tig;
                if (c0     > r0)     s[j][0] = -INFINITY;
                if (c0 + 1 > r0)     s[j][1] = -INFINITY;
                if (c0     > r0 + 8) s[j][2] = -INFINITY;
                if (c0 + 1 > r0 + 8) s[j][3] = -INFINITY;
            }
        }

        // Online softmax (rows gid and gid+8).
        float mx0 = -INFINITY, mx1 = -INFINITY;
        #pragma unroll
        for (int j = 0; j < 8; j++) {
            mx0 = fmaxf(mx0, fmaxf(s[j][0], s[j][1]));
            mx1 = fmaxf(mx1, fmaxf(s[j][2], s[j][3]));
        }
        mx0 = fmaxf(mx0, __shfl_xor_sync(0xffffffffu, mx0, 1));
        mx0 = fmaxf(mx0, __shfl_xor_sync(0xffffffffu, mx0, 2));
        mx1 = fmaxf(mx1, __shfl_xor_sync(0xffffffffu, mx1, 1));
        mx1 = fmaxf(mx1, __shfl_xor_sync(0xffffffffu, mx1, 2));
        float mn0 = fmaxf(mrow0, mx0), mn1 = fmaxf(mrow1, mx1);
        float al0 = __expf(mrow0 - mn0), al1 = __expf(mrow1 - mn1);
        float rs0 = 0.0f, rs1 = 0.0f;
        #pragma unroll
        for (int j = 0; j < 8; j++) {
            s[j][0] = __expf(s[j][0] - mn0);
            s[j][1] = __expf(s[j][1] - mn0);
            s[j][2] = __expf(s[j][2] - mn1);
            s[j][3] = __expf(s[j][3] - mn1);
            rs0 += s[j][0] + s[j][1];
            rs1 += s[j][2] + s[j][3];
        }
        rs0 += __shfl_xor_sync(0xffffffffu, rs0, 1);
        rs0 += __shfl_xor_sync(0xffffffffu, rs0, 2);
        rs1 += __shfl_xor_sync(0xffffffffu, rs1, 1);
        rs1 += __shfl_xor_sync(0xffffffffu, rs1, 2);
        lrow0 = lrow0 * al0 + rs0;
        lrow1 = lrow1 * al1 + rs1;
        mrow0 = mn0; mrow1 = mn1;
        #pragma unroll
        for (int j = 0; j < 8; j++) {
            o[j][0] *= al0; o[j][1] *= al0;
            o[j][2] *= al1; o[j][3] *= al1;
        }

        // Pack P accumulator into A-fragments (split hi/lo).
        uint32_t ph[4][4], pl[4][4];
        #pragma unroll
        for (int kc = 0; kc < 4; kc++) {
            int j0 = 2 * kc, j1 = 2 * kc + 1;
            split2(s[j0][0], s[j0][1], ph[kc][0], pl[kc][0]);
            split2(s[j0][2], s[j0][3], ph[kc][1], pl[kc][1]);
            split2(s[j1][0], s[j1][1], ph[kc][2], pl[kc][2]);
            split2(s[j1][2], s[j1][3], ph[kc][3], pl[kc][3]);
        }

        // O += P V (split-fp16).
        #pragma unroll
        for (int kc = 0; kc < 4; kc++) {
            #pragma unroll
            for (int j = 0; j < 8; j += 2) {
                int key  = kc * 16 + (lane & 7) + ((lane & 8) ? 8 : 0);
                int dcol = 8 * j + (lane >> 4) * 8;
                uint32_t vh[4], vl[4];
                ldsm_x4t(vh, su32(&Vh[key * KS_ + dcol]));
                ldsm_x4t(vl, su32(&Vl[key * KS_ + dcol]));
                mma16816(o[j],     ph[kc], vh);
                mma16816(o[j],     ph[kc], vl);
                mma16816(o[j],     pl[kc], vh);
                mma16816(o[j + 1], ph[kc], vh + 2);
                mma16816(o[j + 1], ph[kc], vl + 2);
                mma16816(o[j + 1], pl[kc], vh + 2);
            }
        }
        __syncthreads();   // stage p reads done before nt+1 issues into it
    }

    // Epilogue: normalize, store fp32.
    float inv0 = 1.0f / lrow0, inv1 = 1.0f / lrow1;
    const int r0 = m0 + wid * 16 + gid;
    float* ob = out + (size_t)b * T_ * D_;
    #pragma unroll
    for (int j = 0; j < 8; j++) {
        int c = 8 * j + 2 * tig;
        *(float2*)&ob[(size_t)r0 * D_ + c] =
            make_float2(o[j][0] * inv0, o[j][1] * inv0);
        *(float2*)&ob[(size_t)(r0 + 8) * D_ + c] =
            make_float2(o[j][2] * inv1, o[j][3] * inv1);
    }
}

// ---------------------------------------------------------------------------
extern "C" void kernel_launch(void* const* d_in, const int* in_sizes, int n_in,
                              void* d_out, int out_size)
{
    const float* x  = (const float*)d_in[0];
    const float* Wq = (const float*)d_in[1];
    const float* bq = (const float*)d_in[2];
    const float* Wk = (const float*)d_in[3];
    const float* bk = (const float*)d_in[4];
    const float* Wv = (const float*)d_in[5];
    const float* bv = (const float*)d_in[6];
    float* out = (float*)d_out;

    cudaFuncSetAttribute(qkv_proj_kernel,
                         cudaFuncAttributeMaxDynamicSharedMemorySize, PROJ_SMEM);
    cudaFuncSetAttribute(flash_attn_kernel,
                         cudaFuncAttributeMaxDynamicSharedMemorySize, ATTN_SMEM);

    wprep_kernel<<<(E_ * NC_ + 255) / 256, 256>>>(Wq, Wk, Wv);
    qkv_proj_kernel<<<BT_ / 64, 256, PROJ_SMEM>>>(x, bq, bk, bv);
    dim3 gattn(T_ / 64, B_);
    flash_attn_kernel<<<gattn, 128, ATTN_SMEM>>>(out);
}

// round 8
// speedup vs baseline: 1.3594x; 1.3594x over previous
#include <cuda_runtime.h>
#include <cuda_fp16.h>
#include <math.h>
#include <stdint.h>

constexpr int B_ = 8, T_ = 2048, E_ = 1024, D_ = 64;
constexpr int BT_ = B_ * T_;
constexpr int NC_ = 192;   // concatenated q|k|v columns

// Projection outputs: hi halves for q|k|v, lo halves only for q (register-side
// split operand in attention). W prepacked hi halves only.
__device__ __half g_hi[BT_ * NC_];
__device__ __half g_lo[BT_ * NC_];   // only cols 0..63 (q) are written/read
__device__ __half g_whi[E_ * NC_];

// ---------------------------------------------------------------------------
// Helpers
// ---------------------------------------------------------------------------
__device__ __forceinline__ uint32_t su32(const void* p) {
    return (uint32_t)__cvta_generic_to_shared(p);
}
__device__ __forceinline__ void ldsm_x4(uint32_t* r, uint32_t a) {
    asm volatile("ldmatrix.sync.aligned.m8n8.x4.shared.b16 {%0,%1,%2,%3}, [%4];"
                 : "=r"(r[0]), "=r"(r[1]), "=r"(r[2]), "=r"(r[3]) : "r"(a));
}
__device__ __forceinline__ void ldsm_x4t(uint32_t* r, uint32_t a) {
    asm volatile("ldmatrix.sync.aligned.m8n8.x4.trans.shared.b16 {%0,%1,%2,%3}, [%4];"
                 : "=r"(r[0]), "=r"(r[1]), "=r"(r[2]), "=r"(r[3]) : "r"(a));
}
__device__ __forceinline__ void mma16816(float* c, const uint32_t* a, const uint32_t* b) {
    asm volatile("mma.sync.aligned.m16n8k16.row.col.f32.f16.f16.f32 "
                 "{%0,%1,%2,%3},{%4,%5,%6,%7},{%8,%9},{%0,%1,%2,%3};"
                 : "+f"(c[0]), "+f"(c[1]), "+f"(c[2]), "+f"(c[3])
                 : "r"(a[0]), "r"(a[1]), "r"(a[2]), "r"(a[3]), "r"(b[0]), "r"(b[1]));
}
__device__ __forceinline__ void split2(float a, float b, uint32_t& hi, uint32_t& lo) {
    __half ha = __float2half_rn(a), hb = __float2half_rn(b);
    __half2 H = __halves2half2(ha, hb);
    hi = *reinterpret_cast<uint32_t*>(&H);
    __half2 L = __halves2half2(__float2half_rn(a - __half2float(ha)),
                               __float2half_rn(b - __half2float(hb)));
    lo = *reinterpret_cast<uint32_t*>(&L);
}
__device__ __forceinline__ void cp16(void* dst, const void* src) {
    asm volatile("cp.async.cg.shared.global [%0], [%1], 16;"
                 :: "r"(su32(dst)), "l"(src) : "memory");
}
__device__ __forceinline__ void cp_commit() {
    asm volatile("cp.async.commit_group;" ::: "memory");
}
template <int N> __device__ __forceinline__ void cp_wait() {
    asm volatile("cp.async.wait_group %0;" :: "n"(N) : "memory");
}

// ---------------------------------------------------------------------------
// W prepack: [1024 x 192] hi halves only.
// ---------------------------------------------------------------------------
__global__ void wprep_kernel(const float* __restrict__ Wq,
                             const float* __restrict__ Wk,
                             const float* __restrict__ Wv) {
    int idx = blockIdx.x * 256 + threadIdx.x;
    if (idx >= E_ * NC_) return;
    int k = idx / NC_, c = idx % NC_;
    float w = (c < 64) ? Wq[k * 64 + c] : (c < 128) ? Wk[k * 64 + c - 64]
                                                    : Wv[k * 64 + c - 128];
    g_whi[idx] = __float2half_rn(w);
}

// ---------------------------------------------------------------------------
// Fused QKV projection: C = (xh + xl) * Wh  (2-term split, W fp16).
// BM=64, BN=192, BK=32, 8 warps (4m x 2n), warp tile 16x96, double-buffered.
// Epilogue: bias, q pre-scale 0.125, hi store (lo store for q cols only).
// ---------------------------------------------------------------------------
constexpr int XS_ = 40;    // xs row stride (halves)
constexpr int WS_ = 200;   // ws row stride (halves)
constexpr int PXS = 64 * XS_;           // 2560 halves per x buffer
constexpr int PWS = 32 * WS_;           // 6400 halves per w buffer
constexpr int PSTG = 2 * PXS + PWS;     // halves per stage (11520)

__global__ __launch_bounds__(256) void qkv_proj_kernel(
    const float* __restrict__ x,
    const float* __restrict__ bq, const float* __restrict__ bk,
    const float* __restrict__ bv)
{
    __shared__ __align__(16) __half Ps[2 * PSTG];   // 46,080 B static

    const int tid = threadIdx.x, wid = tid >> 5, lane = tid & 31;
    const int gid = lane >> 2, tig = lane & 3;
    const int m0 = blockIdx.x * 64;
    const int wm = (wid >> 1) * 16, wn = (wid & 1) * 96;

    float acc[12][4];
    #pragma unroll
    for (int j = 0; j < 12; j++)
        #pragma unroll
        for (int c = 0; c < 4; c++) acc[j][c] = 0.0f;

    // Prologue: x chunk 0 into regs, W chunk 0 into stage 0 via cp.async.
    float4 xv[2];
    #pragma unroll
    for (int i = 0; i < 2; i++) {
        int lin = tid + i * 256;
        xv[i] = *(const float4*)&x[(size_t)(m0 + (lin >> 3)) * E_ + (lin & 7) * 4];
    }
    {
        __half* wh = Ps + 2 * PXS;
        #pragma unroll
        for (int i = 0; i < 3; i++) {
            int lin = tid + i * 256;
            int r = lin / 24, cg = lin % 24;
            cp16(&wh[r * WS_ + cg * 8], &g_whi[(size_t)r * NC_ + cg * 8]);
        }
        cp_commit();
    }

    for (int c = 0; c < E_ / 32; c++) {
        const int p = c & 1;
        __half* xh = Ps + p * PSTG;
        __half* xl = xh + PXS;
        __half* wh = xl + PXS;

        // Store prefetched x regs (split) into stage p.
        #pragma unroll
        for (int i = 0; i < 2; i++) {
            int lin = tid + i * 256;
            int r = lin >> 3, cg = lin & 7;
            uint32_t h0, l0, h1, l1;
            split2(xv[i].x, xv[i].y, h0, l0);
            split2(xv[i].z, xv[i].w, h1, l1);
            *(uint32_t*)&xh[r * XS_ + cg * 4]     = h0;
            *(uint32_t*)&xh[r * XS_ + cg * 4 + 2] = h1;
            *(uint32_t*)&xl[r * XS_ + cg * 4]     = l0;
            *(uint32_t*)&xl[r * XS_ + cg * 4 + 2] = l1;
        }

        if (c + 1 < E_ / 32) {
            const int k1 = (c + 1) * 32;
            #pragma unroll
            for (int i = 0; i < 2; i++) {
                int lin = tid + i * 256;
                xv[i] = *(const float4*)&x[(size_t)(m0 + (lin >> 3)) * E_ + k1 + (lin & 7) * 4];
            }
            __half* nwh = Ps + (p ^ 1) * PSTG + 2 * PXS;
            #pragma unroll
            for (int i = 0; i < 3; i++) {
                int lin = tid + i * 256;
                int r = lin / 24, cg = lin % 24;
                cp16(&nwh[r * WS_ + cg * 8], &g_whi[(size_t)(k1 + r) * NC_ + cg * 8]);
            }
            cp_commit();
            cp_wait<1>();
        } else {
            cp_wait<0>();
        }
        __syncthreads();

        #pragma unroll
        for (int kc = 0; kc < 2; kc++) {
            uint32_t ah[4], al[4];
            int arow = wm + (lane & 15);
            int acol = kc * 16 + (lane >> 4) * 8;
            ldsm_x4(ah, su32(&xh[arow * XS_ + acol]));
            ldsm_x4(al, su32(&xl[arow * XS_ + acol]));
            #pragma unroll
            for (int j = 0; j < 12; j += 2) {
                uint32_t bh[4];
                int brow = kc * 16 + (lane & 15);
                int bcol = wn + 8 * j + (lane >> 4) * 8;
                ldsm_x4t(bh, su32(&wh[brow * WS_ + bcol]));
                mma16816(acc[j],     ah, bh);
                mma16816(acc[j],     al, bh);
                mma16816(acc[j + 1], ah, bh + 2);
                mma16816(acc[j + 1], al, bh + 2);
            }
        }
        __syncthreads();
    }

    // Epilogue: bias, q pre-scale (exact pow2), split, store.
    const int r0 = m0 + wm + gid;
    #pragma unroll
    for (int j = 0; j < 12; j++) {
        int col = wn + 8 * j + 2 * tig;
        const float* bias = (col < 64) ? bq : (col < 128) ? bk : bv;
        float sc = (col < 64) ? 0.125f : 1.0f;
        int bc = col & 63;
        float b0 = bias[bc], b1 = bias[bc + 1];
        uint32_t hi, lo;
        split2((acc[j][0] + b0) * sc, (acc[j][1] + b1) * sc, hi, lo);
        *(uint32_t*)&g_hi[(size_t)r0 * NC_ + col] = hi;
        if (col < 64) *(uint32_t*)&g_lo[(size_t)r0 * NC_ + col] = lo;
        split2((acc[j][2] + b0) * sc, (acc[j][3] + b1) * sc, hi, lo);
        *(uint32_t*)&g_hi[(size_t)(r0 + 8) * NC_ + col] = hi;
        if (col < 64) *(uint32_t*)&g_lo[(size_t)(r0 + 8) * NC_ + col] = lo;
    }
}

// ---------------------------------------------------------------------------
// Flash attention on HMMA, 2-term splits:
//   S = (qh + ql) * kh,   O = (ph + pl) * vh.
// Br=64, Bc=64, 4 warps; K/V hi-only in smem, double-buffered via cp.async.
// Q pre-scaled by 0.125 in projection.
// ---------------------------------------------------------------------------
constexpr int KS_ = 72;        // smem row stride (halves)
constexpr int ATS = 64 * KS_;  // halves per K/V buffer (4608)
constexpr int ASTG = 2 * ATS;  // halves per stage (Kh, Vh)

__global__ __launch_bounds__(128) void flash_attn_kernel(float* __restrict__ out)
{
    __shared__ __align__(16) __half As[2 * ASTG];   // 36,864 B static

    const int tid = threadIdx.x, wid = tid >> 5, lane = tid & 31;
    const int gid = lane >> 2, tig = lane & 3;
    const int b = blockIdx.y;
    const int qt = (T_ / 64 - 1) - blockIdx.x;   // heavy tiles first
    const int m0 = qt * 64;
    const int rowbase = b * T_;

    auto issue_tile = [&](int nt, int st) {
        __half* Kh = As + st * ASTG;
        __half* Vh = Kh + ATS;
        const int n0 = nt * 64;
        #pragma unroll
        for (int i = 0; i < 4; i++) {
            int lin = tid + i * 128;
            int r = lin >> 3, cg = lin & 7;
            const size_t g = (size_t)(rowbase + n0 + r) * NC_;
            cp16(&Kh[r * KS_ + cg * 8], &g_hi[g + 64 + cg * 8]);
            cp16(&Vh[r * KS_ + cg * 8], &g_hi[g + 128 + cg * 8]);
        }
        cp_commit();
    };

    issue_tile(0, 0);

    // Q fragments (hi and lo), 4 k-chunks of 16. Pre-scaled by 0.125.
    uint32_t qh[4][4], ql[4][4];
    {
        const size_t r0 = (size_t)(rowbase + m0 + wid * 16 + gid) * NC_;
        #pragma unroll
        for (int kc = 0; kc < 4; kc++) {
            int c0 = kc * 16 + 2 * tig;
            qh[kc][0] = *(const uint32_t*)&g_hi[r0 + c0];
            qh[kc][1] = *(const uint32_t*)&g_hi[r0 + 8 * NC_ + c0];
            qh[kc][2] = *(const uint32_t*)&g_hi[r0 + c0 + 8];
            qh[kc][3] = *(const uint32_t*)&g_hi[r0 + 8 * NC_ + c0 + 8];
            ql[kc][0] = *(const uint32_t*)&g_lo[r0 + c0];
            ql[kc][1] = *(const uint32_t*)&g_lo[r0 + 8 * NC_ + c0];
            ql[kc][2] = *(const uint32_t*)&g_lo[r0 + c0 + 8];
            ql[kc][3] = *(const uint32_t*)&g_lo[r0 + 8 * NC_ + c0 + 8];
        }
    }

    float o[8][4];
    #pragma unroll
    for (int j = 0; j < 8; j++)
        #pragma unroll
        for (int c = 0; c < 4; c++) o[j][c] = 0.0f;
    float mrow0 = -INFINITY, mrow1 = -INFINITY, lrow0 = 0.0f, lrow1 = 0.0f;

    for (int nt = 0; nt <= qt; nt++) {
        const int n0 = nt * 64;
        const int p = nt & 1;
        __half* Kh = As + p * ASTG;
        __half* Vh = Kh + ATS;

        if (nt < qt) { issue_tile(nt + 1, p ^ 1); cp_wait<1>(); }
        else         { cp_wait<0>(); }
        __syncthreads();

        // S = (qh + ql) * kh.
        float s[8][4];
        #pragma unroll
        for (int j = 0; j < 8; j++)
            #pragma unroll
            for (int c = 0; c < 4; c++) s[j][c] = 0.0f;

        #pragma unroll
        for (int kc = 0; kc < 4; kc++) {
            #pragma unroll
            for (int j = 0; j < 8; j += 2) {
                int key = 8 * j + (lane >> 4) * 8 + (lane & 7);
                int c   = kc * 16 + ((lane >> 3) & 1) * 8;
                uint32_t kh[4];
                ldsm_x4(kh, su32(&Kh[key * KS_ + c]));
                mma16816(s[j],     qh[kc], kh);
                mma16816(s[j],     ql[kc], kh);
                mma16816(s[j + 1], qh[kc], kh + 2);
                mma16816(s[j + 1], ql[kc], kh + 2);
            }
        }

        // Causal mask (diagonal tile only; scale folded into Q).
        if (nt == qt) {
            int r0 = m0 + wid * 16 + gid;
            #pragma unroll
            for (int j = 0; j < 8; j++) {
                int c0 = n0 + 8 * j + 2 * tig;
                if (c0     > r0)     s[j][0] = -INFINITY;
                if (c0 + 1 > r0)     s[j][1] = -INFINITY;
                if (c0     > r0 + 8) s[j][2] = -INFINITY;
                if (c0 + 1 > r0 + 8) s[j][3] = -INFINITY;
            }
        }

        // Online softmax (rows gid and gid+8).
        float mx0 = -INFINITY, mx1 = -INFINITY;
        #pragma unroll
        for (int j = 0; j < 8; j++) {
            mx0 = fmaxf(mx0, fmaxf(s[j][0], s[j][1]));
            mx1 = fmaxf(mx1, fmaxf(s[j][2], s[j][3]));
        }
        mx0 = fmaxf(mx0, __shfl_xor_sync(0xffffffffu, mx0, 1));
        mx0 = fmaxf(mx0, __shfl_xor_sync(0xffffffffu, mx0, 2));
        mx1 = fmaxf(mx1, __shfl_xor_sync(0xffffffffu, mx1, 1));
        mx1 = fmaxf(mx1, __shfl_xor_sync(0xffffffffu, mx1, 2));
        float mn0 = fmaxf(mrow0, mx0), mn1 = fmaxf(mrow1, mx1);
        float al0 = __expf(mrow0 - mn0), al1 = __expf(mrow1 - mn1);
        float rs0 = 0.0f, rs1 = 0.0f;
        #pragma unroll
        for (int j = 0; j < 8; j++) {
            s[j][0] = __expf(s[j][0] - mn0);
            s[j][1] = __expf(s[j][1] - mn0);
            s[j][2] = __expf(s[j][2] - mn1);
            s[j][3] = __expf(s[j][3] - mn1);
            rs0 += s[j][0] + s[j][1];
            rs1 += s[j][2] + s[j][3];
        }
        rs0 += __shfl_xor_sync(0xffffffffu, rs0, 1);
        rs0 += __shfl_xor_sync(0xffffffffu, rs0, 2);
        rs1 += __shfl_xor_sync(0xffffffffu, rs1, 1);
        rs1 += __shfl_xor_sync(0xffffffffu, rs1, 2);
        lrow0 = lrow0 * al0 + rs0;
        lrow1 = lrow1 * al1 + rs1;
        mrow0 = mn0; mrow1 = mn1;
        #pragma unroll
        for (int j = 0; j < 8; j++) {
            o[j][0] *= al0; o[j][1] *= al0;
            o[j][2] *= al1; o[j][3] *= al1;
        }

        // Pack P accumulator into split A-fragments.
        uint32_t ph[4][4], pl[4][4];
        #pragma unroll
        for (int kc = 0; kc < 4; kc++) {
            int j0 = 2 * kc, j1 = 2 * kc + 1;
            split2(s[j0][0], s[j0][1], ph[kc][0], pl[kc][0]);
            split2(s[j0][2], s[j0][3], ph[kc][1], pl[kc][1]);
            split2(s[j1][0], s[j1][1], ph[kc][2], pl[kc][2]);
            split2(s[j1][2], s[j1][3], ph[kc][3], pl[kc][3]);
        }

        // O += (ph + pl) * vh.
        #pragma unroll
        for (int kc = 0; kc < 4; kc++) {
            #pragma unroll
            for (int j = 0; j < 8; j += 2) {
                int key  = kc * 16 + (lane & 7) + ((lane & 8) ? 8 : 0);
                int dcol = 8 * j + (lane >> 4) * 8;
                uint32_t vh[4];
                ldsm_x4t(vh, su32(&Vh[key * KS_ + dcol]));
                mma16816(o[j],     ph[kc], vh);
                mma16816(o[j],     pl[kc], vh);
                mma16816(o[j + 1], ph[kc], vh + 2);
                mma16816(o[j + 1], pl[kc], vh + 2);
            }
        }
        __syncthreads();   // stage p reads done before nt+1 issues into it
    }

    // Epilogue: normalize, store fp32.
    float inv0 = 1.0f / lrow0, inv1 = 1.0f / lrow1;
    const int r0 = m0 + wid * 16 + gid;
    float* ob = out + (size_t)b * T_ * D_;
    #pragma unroll
    for (int j = 0; j < 8; j++) {
        int c = 8 * j + 2 * tig;
        *(float2*)&ob[(size_t)r0 * D_ + c] =
            make_float2(o[j][0] * inv0, o[j][1] * inv0);
        *(float2*)&ob[(size_t)(r0 + 8) * D_ + c] =
            make_float2(o[j][2] * inv1, o[j][3] * inv1);
    }
}

// ---------------------------------------------------------------------------
extern "C" void kernel_launch(void* const* d_in, const int* in_sizes, int n_in,
                              void* d_out, int out_size)
{
    const float* x  = (const float*)d_in[0];
    const float* Wq = (const float*)d_in[1];
    const float* bq = (const float*)d_in[2];
    const float* Wk = (const float*)d_in[3];
    const float* bk = (const float*)d_in[4];
    const float* Wv = (const float*)d_in[5];
    const float* bv = (const float*)d_in[6];
    float* out = (float*)d_out;

    wprep_kernel<<<(E_ * NC_ + 255) / 256, 256>>>(Wq, Wk, Wv);
    qkv_proj_kernel<<<BT_ / 64, 256>>>(x, bq, bk, bv);
    dim3 gattn(T_ / 64, B_);
    flash_attn_kernel<<<gattn, 128>>>(out);
}

// round 12
// speedup vs baseline: 2.1178x; 1.5579x over previous
#include <cuda_runtime.h>
#include <cuda_fp16.h>
#include <math.h>
#include <stdint.h>

constexpr int B_ = 8, T_ = 2048, E_ = 1024, D_ = 64;
constexpr int BT_ = B_ * T_;
constexpr int NC_ = 192;   // concatenated q|k|v columns

// Projection outputs (fp16; q pre-scaled by 0.125) and prepacked fp16 W.
__device__ __half g_hi[BT_ * NC_];
__device__ __half g_whi[E_ * NC_];

// ---------------------------------------------------------------------------
// Helpers
// ---------------------------------------------------------------------------
__device__ __forceinline__ uint32_t su32(const void* p) {
    return (uint32_t)__cvta_generic_to_shared(p);
}
__device__ __forceinline__ void ldsm_x4(uint32_t* r, uint32_t a) {
    asm volatile("ldmatrix.sync.aligned.m8n8.x4.shared.b16 {%0,%1,%2,%3}, [%4];"
                 : "=r"(r[0]), "=r"(r[1]), "=r"(r[2]), "=r"(r[3]) : "r"(a));
}
__device__ __forceinline__ void ldsm_x4t(uint32_t* r, uint32_t a) {
    asm volatile("ldmatrix.sync.aligned.m8n8.x4.trans.shared.b16 {%0,%1,%2,%3}, [%4];"
                 : "=r"(r[0]), "=r"(r[1]), "=r"(r[2]), "=r"(r[3]) : "r"(a));
}
__device__ __forceinline__ void mma16816(float* c, const uint32_t* a, const uint32_t* b) {
    asm volatile("mma.sync.aligned.m16n8k16.row.col.f32.f16.f16.f32 "
                 "{%0,%1,%2,%3},{%4,%5,%6,%7},{%8,%9},{%0,%1,%2,%3};"
                 : "+f"(c[0]), "+f"(c[1]), "+f"(c[2]), "+f"(c[3])
                 : "r"(a[0]), "r"(a[1]), "r"(a[2]), "r"(a[3]), "r"(b[0]), "r"(b[1]));
}
__device__ __forceinline__ uint32_t pack2(float a, float b) {
    __half2 h = __floats2half2_rn(a, b);
    return *reinterpret_cast<uint32_t*>(&h);
}
__device__ __forceinline__ void cp16(void* dst, const void* src) {
    asm volatile("cp.async.cg.shared.global [%0], [%1], 16;"
                 :: "r"(su32(dst)), "l"(src) : "memory");
}
__device__ __forceinline__ void cp_commit() {
    asm volatile("cp.async.commit_group;" ::: "memory");
}
template <int N> __device__ __forceinline__ void cp_wait() {
    asm volatile("cp.async.wait_group %0;" :: "n"(N) : "memory");
}

// ---------------------------------------------------------------------------
// W prepack: [1024 x 192] fp16, vectorized x4.
// ---------------------------------------------------------------------------
__global__ void wprep_kernel(const float* __restrict__ Wq,
                             const float* __restrict__ Wk,
                             const float* __restrict__ Wv) {
    int idx4 = blockIdx.x * 256 + threadIdx.x;      // handles 4 elements
    if (idx4 >= E_ * NC_ / 4) return;
    int idx = idx4 * 4;
    int k = idx / NC_, c = idx % NC_;               // c is 4-aligned, one segment
    const float* W = (c < 64) ? &Wq[k * 64 + c] : (c < 128) ? &Wk[k * 64 + c - 64]
                                                            : &Wv[k * 64 + c - 128];
    float4 w = *(const float4*)W;
    uint2 out = make_uint2(pack2(w.x, w.y), pack2(w.z, w.w));
    *(uint2*)&g_whi[idx] = out;
}

// ---------------------------------------------------------------------------
// Fused QKV projection: C = xh * Wh (pure fp16 operands, fp32 accum).
// BM=64, BN=192, BK=32, 8 warps (4m x 2n), warp tile 16x96, double-buffered.
// Epilogue: bias add, q-columns pre-scaled by 0.125, fp16 store.
// ---------------------------------------------------------------------------
constexpr int XS_ = 40;    // xs row stride (halves)
constexpr int WS_ = 200;   // ws row stride (halves)
constexpr int PXS = 64 * XS_;        // 2560 halves per x buffer
constexpr int PWS = 32 * WS_;        // 6400 halves per w buffer
constexpr int PSTG = PXS + PWS;      // halves per stage (8960)

__global__ __launch_bounds__(256) void qkv_proj_kernel(
    const float* __restrict__ x,
    const float* __restrict__ bq, const float* __restrict__ bk,
    const float* __restrict__ bv)
{
    __shared__ __align__(16) __half Ps[2 * PSTG];   // 35,840 B static

    const int tid = threadIdx.x, wid = tid >> 5, lane = tid & 31;
    const int gid = lane >> 2, tig = lane & 3;
    const int m0 = blockIdx.x * 64;
    const int wm = (wid >> 1) * 16, wn = (wid & 1) * 96;

    float acc[12][4];
    #pragma unroll
    for (int j = 0; j < 12; j++)
        #pragma unroll
        for (int c = 0; c < 4; c++) acc[j][c] = 0.0f;

    // Prologue: x chunk 0 into regs, W chunk 0 into stage 0 via cp.async.
    float4 xv[2];
    #pragma unroll
    for (int i = 0; i < 2; i++) {
        int lin = tid + i * 256;
        xv[i] = *(const float4*)&x[(size_t)(m0 + (lin >> 3)) * E_ + (lin & 7) * 4];
    }
    {
        __half* wh = Ps + PXS;
        #pragma unroll
        for (int i = 0; i < 3; i++) {
            int lin = tid + i * 256;
            int r = lin / 24, cg = lin % 24;
            cp16(&wh[r * WS_ + cg * 8], &g_whi[(size_t)r * NC_ + cg * 8]);
        }
        cp_commit();
    }

    for (int c = 0; c < E_ / 32; c++) {
        const int p = c & 1;
        __half* xh = Ps + p * PSTG;
        __half* wh = xh + PXS;

        // Store prefetched x regs (fp16) into stage p.
        #pragma unroll
        for (int i = 0; i < 2; i++) {
            int lin = tid + i * 256;
            int r = lin >> 3, cg = lin & 7;
            *(uint2*)&xh[r * XS_ + cg * 4] =
                make_uint2(pack2(xv[i].x, xv[i].y), pack2(xv[i].z, xv[i].w));
        }

        if (c + 1 < E_ / 32) {
            const int k1 = (c + 1) * 32;
            #pragma unroll
            for (int i = 0; i < 2; i++) {
                int lin = tid + i * 256;
                xv[i] = *(const float4*)&x[(size_t)(m0 + (lin >> 3)) * E_ + k1 + (lin & 7) * 4];
            }
            __half* nwh = Ps + (p ^ 1) * PSTG + PXS;
            #pragma unroll
            for (int i = 0; i < 3; i++) {
                int lin = tid + i * 256;
                int r = lin / 24, cg = lin % 24;
                cp16(&nwh[r * WS_ + cg * 8], &g_whi[(size_t)(k1 + r) * NC_ + cg * 8]);
            }
            cp_commit();
            cp_wait<1>();
        } else {
            cp_wait<0>();
        }
        __syncthreads();

        #pragma unroll
        for (int kc = 0; kc < 2; kc++) {
            uint32_t ah[4];
            int arow = wm + (lane & 15);
            int acol = kc * 16 + (lane >> 4) * 8;
            ldsm_x4(ah, su32(&xh[arow * XS_ + acol]));
            #pragma unroll
            for (int j = 0; j < 12; j += 2) {
                uint32_t bh[4];
                int brow = kc * 16 + (lane & 15);
                int bcol = wn + 8 * j + (lane >> 4) * 8;
                ldsm_x4t(bh, su32(&wh[brow * WS_ + bcol]));
                mma16816(acc[j],     ah, bh);
                mma16816(acc[j + 1], ah, bh + 2);
            }
        }
        __syncthreads();
    }

    // Epilogue: bias, q pre-scale (exact pow2), fp16 store.
    const int r0 = m0 + wm + gid;
    #pragma unroll
    for (int j = 0; j < 12; j++) {
        int col = wn + 8 * j + 2 * tig;
        const float* bias = (col < 64) ? bq : (col < 128) ? bk : bv;
        float sc = (col < 64) ? 0.125f : 1.0f;
        int bc = col & 63;
        float b0 = bias[bc], b1 = bias[bc + 1];
        *(uint32_t*)&g_hi[(size_t)r0 * NC_ + col] =
            pack2((acc[j][0] + b0) * sc, (acc[j][1] + b1) * sc);
        *(uint32_t*)&g_hi[(size_t)(r0 + 8) * NC_ + col] =
            pack2((acc[j][2] + b0) * sc, (acc[j][3] + b1) * sc);
    }
}

// ---------------------------------------------------------------------------
// Flash attention, pure fp16 HMMA (fp32 accum, fp32 softmax).
// Br=64, Bc=64, 4 warps; K/V double-buffered via cp.async.
// Q pre-scaled by 0.125 in projection.
// ---------------------------------------------------------------------------
constexpr int KS_ = 72;        // smem row stride (halves)
constexpr int ATS = 64 * KS_;  // halves per K/V buffer (4608)
constexpr int ASTG = 2 * ATS;  // halves per stage (Kh, Vh)

__global__ __launch_bounds__(128) void flash_attn_kernel(float* __restrict__ out)
{
    __shared__ __align__(16) __half As[2 * ASTG];   // 36,864 B static

    const int tid = threadIdx.x, wid = tid >> 5, lane = tid & 31;
    const int gid = lane >> 2, tig = lane & 3;
    const int b = blockIdx.y;
    const int qt = (T_ / 64 - 1) - blockIdx.x;   // heavy tiles first
    const int m0 = qt * 64;
    const int rowbase = b * T_;

    auto issue_tile = [&](int nt, int st) {
        __half* Kh = As + st * ASTG;
        __half* Vh = Kh + ATS;
        const int n0 = nt * 64;
        #pragma unroll
        for (int i = 0; i < 4; i++) {
            int lin = tid + i * 128;
            int r = lin >> 3, cg = lin & 7;
            const size_t g = (size_t)(rowbase + n0 + r) * NC_;
            cp16(&Kh[r * KS_ + cg * 8], &g_hi[g + 64 + cg * 8]);
            cp16(&Vh[r * KS_ + cg * 8], &g_hi[g + 128 + cg * 8]);
        }
        cp_commit();
    };

    issue_tile(0, 0);

    // Q fragments (fp16, pre-scaled), 4 k-chunks of 16.
    uint32_t qh[4][4];
    {
        const size_t r0 = (size_t)(rowbase + m0 + wid * 16 + gid) * NC_;
        #pragma unroll
        for (int kc = 0; kc < 4; kc++) {
            int c0 = kc * 16 + 2 * tig;
            qh[kc][0] = *(const uint32_t*)&g_hi[r0 + c0];
            qh[kc][1] = *(const uint32_t*)&g_hi[r0 + 8 * NC_ + c0];
            qh[kc][2] = *(const uint32_t*)&g_hi[r0 + c0 + 8];
            qh[kc][3] = *(const uint32_t*)&g_hi[r0 + 8 * NC_ + c0 + 8];
        }
    }

    float o[8][4];
    #pragma unroll
    for (int j = 0; j < 8; j++)
        #pragma unroll
        for (int c = 0; c < 4; c++) o[j][c] = 0.0f;
    float mrow0 = -INFINITY, mrow1 = -INFINITY, lrow0 = 0.0f, lrow1 = 0.0f;

    for (int nt = 0; nt <= qt; nt++) {
        const int n0 = nt * 64;
        const int p = nt & 1;
        __half* Kh = As + p * ASTG;
        __half* Vh = Kh + ATS;

        if (nt < qt) { issue_tile(nt + 1, p ^ 1); cp_wait<1>(); }
        else         { cp_wait<0>(); }
        __syncthreads();

        // S = qh * kh.
        float s[8][4];
        #pragma unroll
        for (int j = 0; j < 8; j++)
            #pragma unroll
            for (int c = 0; c < 4; c++) s[j][c] = 0.0f;

        #pragma unroll
        for (int kc = 0; kc < 4; kc++) {
            #pragma unroll
            for (int j = 0; j < 8; j += 2) {
                int key = 8 * j + (lane >> 4) * 8 + (lane & 7);
                int c   = kc * 16 + ((lane >> 3) & 1) * 8;
                uint32_t kh[4];
                ldsm_x4(kh, su32(&Kh[key * KS_ + c]));
                mma16816(s[j],     qh[kc], kh);
                mma16816(s[j + 1], qh[kc], kh + 2);
            }
        }

        // Causal mask (diagonal tile only; scale folded into Q).
        if (nt == qt) {
            int r0 = m0 + wid * 16 + gid;
            #pragma unroll
            for (int j = 0; j < 8; j++) {
                int c0 = n0 + 8 * j + 2 * tig;
                if (c0     > r0)     s[j][0] = -INFINITY;
                if (c0 + 1 > r0)     s[j][1] = -INFINITY;
                if (c0     > r0 + 8) s[j][2] = -INFINITY;
                if (c0 + 1 > r0 + 8) s[j][3] = -INFINITY;
            }
        }

        // Online softmax (rows gid and gid+8).
        float mx0 = -INFINITY, mx1 = -INFINITY;
        #pragma unroll
        for (int j = 0; j < 8; j++) {
            mx0 = fmaxf(mx0, fmaxf(s[j][0], s[j][1]));
            mx1 = fmaxf(mx1, fmaxf(s[j][2], s[j][3]));
        }
        mx0 = fmaxf(mx0, __shfl_xor_sync(0xffffffffu, mx0, 1));
        mx0 = fmaxf(mx0, __shfl_xor_sync(0xffffffffu, mx0, 2));
        mx1 = fmaxf(mx1, __shfl_xor_sync(0xffffffffu, mx1, 1));
        mx1 = fmaxf(mx1, __shfl_xor_sync(0xffffffffu, mx1, 2));
        float mn0 = fmaxf(mrow0, mx0), mn1 = fmaxf(mrow1, mx1);
        float al0 = __expf(mrow0 - mn0), al1 = __expf(mrow1 - mn1);
        float rs0 = 0.0f, rs1 = 0.0f;
        #pragma unroll
        for (int j = 0; j < 8; j++) {
            s[j][0] = __expf(s[j][0] - mn0);
            s[j][1] = __expf(s[j][1] - mn0);
            s[j][2] = __expf(s[j][2] - mn1);
            s[j][3] = __expf(s[j][3] - mn1);
            rs0 += s[j][0] + s[j][1];
            rs1 += s[j][2] + s[j][3];
        }
        rs0 += __shfl_xor_sync(0xffffffffu, rs0, 1);
        rs0 += __shfl_xor_sync(0xffffffffu, rs0, 2);
        rs1 += __shfl_xor_sync(0xffffffffu, rs1, 1);
        rs1 += __shfl_xor_sync(0xffffffffu, rs1, 2);
        lrow0 = lrow0 * al0 + rs0;
        lrow1 = lrow1 * al1 + rs1;
        mrow0 = mn0; mrow1 = mn1;
        #pragma unroll
        for (int j = 0; j < 8; j++) {
            o[j][0] *= al0; o[j][1] *= al0;
            o[j][2] *= al1; o[j][3] *= al1;
        }

        // Pack P accumulator into fp16 A-fragments.
        uint32_t ph[4][4];
        #pragma unroll
        for (int kc = 0; kc < 4; kc++) {
            int j0 = 2 * kc, j1 = 2 * kc + 1;
            ph[kc][0] = pack2(s[j0][0], s[j0][1]);
            ph[kc][1] = pack2(s[j0][2], s[j0][3]);
            ph[kc][2] = pack2(s[j1][0], s[j1][1]);
            ph[kc][3] = pack2(s[j1][2], s[j1][3]);
        }

        // O += ph * vh.
        #pragma unroll
        for (int kc = 0; kc < 4; kc++) {
            #pragma unroll
            for (int j = 0; j < 8; j += 2) {
                int key  = kc * 16 + (lane & 7) + ((lane & 8) ? 8 : 0);
                int dcol = 8 * j + (lane >> 4) * 8;
                uint32_t vh[4];
                ldsm_x4t(vh, su32(&Vh[key * KS_ + dcol]));
                mma16816(o[j],     ph[kc], vh);
                mma16816(o[j + 1], ph[kc], vh + 2);
            }
        }
        __syncthreads();   // stage p reads done before nt+1 issues into it
    }

    // Epilogue: normalize, store fp32.
    float inv0 = 1.0f / lrow0, inv1 = 1.0f / lrow1;
    const int r0 = m0 + wid * 16 + gid;
    float* ob = out + (size_t)b * T_ * D_;
    #pragma unroll
    for (int j = 0; j < 8; j++) {
        int c = 8 * j + 2 * tig;
        *(float2*)&ob[(size_t)r0 * D_ + c] =
            make_float2(o[j][0] * inv0, o[j][1] * inv0);
        *(float2*)&ob[(size_t)(r0 + 8) * D_ + c] =
            make_float2(o[j][2] * inv1, o[j][3] * inv1);
    }
}

// ---------------------------------------------------------------------------
extern "C" void kernel_launch(void* const* d_in, const int* in_sizes, int n_in,
                              void* d_out, int out_size)
{
    const float* x  = (const float*)d_in[0];
    const float* Wq = (const float*)d_in[1];
    const float* bq = (const float*)d_in[2];
    const float* Wk = (const float*)d_in[3];
    const float* bk = (const float*)d_in[4];
    const float* Wv = (const float*)d_in[5];
    const float* bv = (const float*)d_in[6];
    float* out = (float*)d_out;

    wprep_kernel<<<(E_ * NC_ / 4 + 255) / 256, 256>>>(Wq, Wk, Wv);
    qkv_proj_kernel<<<BT_ / 64, 256>>>(x, bq, bk, bv);
    dim3 gattn(T_ / 64, B_);
    flash_attn_kernel<<<gattn, 128>>>(out);
}

// round 16
// speedup vs baseline: 2.1258x; 1.0038x over previous
#include <cuda_runtime.h>
#include <cuda_fp16.h>
#include <math.h>
#include <stdint.h>

constexpr int B_ = 8, T_ = 2048, E_ = 1024, D_ = 64;
constexpr int BT_ = B_ * T_;
constexpr int NC_ = 192;   // concatenated q|k|v columns

// Projection outputs (fp16; q pre-scaled by 0.125*log2(e)) and prepacked fp16 W.
__device__ __half g_hi[BT_ * NC_];
__device__ __half g_whi[E_ * NC_];
__device__ unsigned int g_job;     // attention work-queue counter

// ---------------------------------------------------------------------------
// Helpers
// ---------------------------------------------------------------------------
__device__ __forceinline__ uint32_t su32(const void* p) {
    return (uint32_t)__cvta_generic_to_shared(p);
}
__device__ __forceinline__ void ldsm_x4(uint32_t* r, uint32_t a) {
    asm volatile("ldmatrix.sync.aligned.m8n8.x4.shared.b16 {%0,%1,%2,%3}, [%4];"
                 : "=r"(r[0]), "=r"(r[1]), "=r"(r[2]), "=r"(r[3]) : "r"(a));
}
__device__ __forceinline__ void ldsm_x4t(uint32_t* r, uint32_t a) {
    asm volatile("ldmatrix.sync.aligned.m8n8.x4.trans.shared.b16 {%0,%1,%2,%3}, [%4];"
                 : "=r"(r[0]), "=r"(r[1]), "=r"(r[2]), "=r"(r[3]) : "r"(a));
}
__device__ __forceinline__ void mma16816(float* c, const uint32_t* a, const uint32_t* b) {
    asm volatile("mma.sync.aligned.m16n8k16.row.col.f32.f16.f16.f32 "
                 "{%0,%1,%2,%3},{%4,%5,%6,%7},{%8,%9},{%0,%1,%2,%3};"
                 : "+f"(c[0]), "+f"(c[1]), "+f"(c[2]), "+f"(c[3])
                 : "r"(a[0]), "r"(a[1]), "r"(a[2]), "r"(a[3]), "r"(b[0]), "r"(b[1]));
}
__device__ __forceinline__ uint32_t pack2(float a, float b) {
    __half2 h = __floats2half2_rn(a, b);
    return *reinterpret_cast<uint32_t*>(&h);
}
__device__ __forceinline__ float ex2(float x) {
    float y;
    asm("ex2.approx.f32 %0, %1;" : "=f"(y) : "f"(x));
    return y;
}
__device__ __forceinline__ void cp16(void* dst, const void* src) {
    asm volatile("cp.async.cg.shared.global [%0], [%1], 16;"
                 :: "r"(su32(dst)), "l"(src) : "memory");
}
__device__ __forceinline__ void cp_commit() {
    asm volatile("cp.async.commit_group;" ::: "memory");
}
template <int N> __device__ __forceinline__ void cp_wait() {
    asm volatile("cp.async.wait_group %0;" :: "n"(N) : "memory");
}

// ---------------------------------------------------------------------------
// W prepack: [1024 x 192] fp16, vectorized x4. Also resets the attn job queue.
// ---------------------------------------------------------------------------
__global__ void wprep_kernel(const float* __restrict__ Wq,
                             const float* __restrict__ Wk,
                             const float* __restrict__ Wv) {
    int idx4 = blockIdx.x * 256 + threadIdx.x;      // handles 4 elements
    if (idx4 == 0) g_job = 0;                       // reset attn work queue
    if (idx4 >= E_ * NC_ / 4) return;
    int idx = idx4 * 4;
    int k = idx / NC_, c = idx % NC_;               // c is 4-aligned, one segment
    const float* W = (c < 64) ? &Wq[k * 64 + c] : (c < 128) ? &Wk[k * 64 + c - 64]
                                                            : &Wv[k * 64 + c - 128];
    float4 w = *(const float4*)W;
    uint2 out = make_uint2(pack2(w.x, w.y), pack2(w.z, w.w));
    *(uint2*)&g_whi[idx] = out;
}

// ---------------------------------------------------------------------------
// Fused QKV projection: C = xh * Wh (pure fp16 operands, fp32 accum).
// BM=64, BN=192, BK=32, 8 warps (4m x 2n), warp tile 16x96, double-buffered.
// Epilogue: bias add, q-columns pre-scaled by 0.125*log2(e), fp16 store.
// ---------------------------------------------------------------------------
constexpr int XS_ = 40;    // xs row stride (halves)
constexpr int WS_ = 200;   // ws row stride (halves)
constexpr int PXS = 64 * XS_;        // 2560 halves per x buffer
constexpr int PWS = 32 * WS_;        // 6400 halves per w buffer
constexpr int PSTG = PXS + PWS;      // halves per stage (8960)

__global__ __launch_bounds__(256) void qkv_proj_kernel(
    const float* __restrict__ x,
    const float* __restrict__ bq, const float* __restrict__ bk,
    const float* __restrict__ bv)
{
    __shared__ __align__(16) __half Ps[2 * PSTG];   // 35,840 B static

    const int tid = threadIdx.x, wid = tid >> 5, lane = tid & 31;
    const int gid = lane >> 2, tig = lane & 3;
    const int m0 = blockIdx.x * 64;
    const int wm = (wid >> 1) * 16, wn = (wid & 1) * 96;

    float acc[12][4];
    #pragma unroll
    for (int j = 0; j < 12; j++)
        #pragma unroll
        for (int c = 0; c < 4; c++) acc[j][c] = 0.0f;

    // Prologue: x chunk 0 into regs, W chunk 0 into stage 0 via cp.async.
    float4 xv[2];
    #pragma unroll
    for (int i = 0; i < 2; i++) {
        int lin = tid + i * 256;
        xv[i] = *(const float4*)&x[(size_t)(m0 + (lin >> 3)) * E_ + (lin & 7) * 4];
    }
    {
        __half* wh = Ps + PXS;
        #pragma unroll
        for (int i = 0; i < 3; i++) {
            int lin = tid + i * 256;
            int r = lin / 24, cg = lin % 24;
            cp16(&wh[r * WS_ + cg * 8], &g_whi[(size_t)r * NC_ + cg * 8]);
        }
        cp_commit();
    }

    for (int c = 0; c < E_ / 32; c++) {
        const int p = c & 1;
        __half* xh = Ps + p * PSTG;
        __half* wh = xh + PXS;

        // Store prefetched x regs (fp16) into stage p.
        #pragma unroll
        for (int i = 0; i < 2; i++) {
            int lin = tid + i * 256;
            int r = lin >> 3, cg = lin & 7;
            *(uint2*)&xh[r * XS_ + cg * 4] =
                make_uint2(pack2(xv[i].x, xv[i].y), pack2(xv[i].z, xv[i].w));
        }

        if (c + 1 < E_ / 32) {
            const int k1 = (c + 1) * 32;
            #pragma unroll
            for (int i = 0; i < 2; i++) {
                int lin = tid + i * 256;
                xv[i] = *(const float4*)&x[(size_t)(m0 + (lin >> 3)) * E_ + k1 + (lin & 7) * 4];
            }
            __half* nwh = Ps + (p ^ 1) * PSTG + PXS;
            #pragma unroll
            for (int i = 0; i < 3; i++) {
                int lin = tid + i * 256;
                int r = lin / 24, cg = lin % 24;
                cp16(&nwh[r * WS_ + cg * 8], &g_whi[(size_t)(k1 + r) * NC_ + cg * 8]);
            }
            cp_commit();
            cp_wait<1>();
        } else {
            cp_wait<0>();
        }
        __syncthreads();

        #pragma unroll
        for (int kc = 0; kc < 2; kc++) {
            uint32_t ah[4];
            int arow = wm + (lane & 15);
            int acol = kc * 16 + (lane >> 4) * 8;
            ldsm_x4(ah, su32(&xh[arow * XS_ + acol]));
            #pragma unroll
            for (int j = 0; j < 12; j += 2) {
                uint32_t bh[4];
                int brow = kc * 16 + (lane & 15);
                int bcol = wn + 8 * j + (lane >> 4) * 8;
                ldsm_x4t(bh, su32(&wh[brow * WS_ + bcol]));
                mma16816(acc[j],     ah, bh);
                mma16816(acc[j + 1], ah, bh + 2);
            }
        }
        __syncthreads();
    }

    // Epilogue: bias, q pre-scale (0.125 * log2(e) -> exp2-domain logits).
    const float QSC = 0.18033688011112042f;
    const int r0 = m0 + wm + gid;
    #pragma unroll
    for (int j = 0; j < 12; j++) {
        int col = wn + 8 * j + 2 * tig;
        const float* bias = (col < 64) ? bq : (col < 128) ? bk : bv;
        float sc = (col < 64) ? QSC : 1.0f;
        int bc = col & 63;
        float b0 = bias[bc], b1 = bias[bc + 1];
        *(uint32_t*)&g_hi[(size_t)r0 * NC_ + col] =
            pack2((acc[j][0] + b0) * sc, (acc[j][1] + b1) * sc);
        *(uint32_t*)&g_hi[(size_t)(r0 + 8) * NC_ + col] =
            pack2((acc[j][2] + b0) * sc, (acc[j][3] + b1) * sc);
    }
}

// ---------------------------------------------------------------------------
// Flash attention, pure fp16 HMMA (fp32 accum, exp2-domain softmax).
// Persistent CTAs (296) pop (b, qt) jobs heavy-first from an atomic queue.
// Br=64, Bc=64, 4 warps; K/V double-buffered via cp.async.
// ---------------------------------------------------------------------------
constexpr int KS_ = 72;        // smem row stride (halves)
constexpr int ATS = 64 * KS_;  // halves per K/V buffer (4608)
constexpr int ASTG = 2 * ATS;  // halves per stage (Kh, Vh)
constexpr int NJOBS = (T_ / 64) * B_;   // 256
constexpr int NCTAS = 296;

__global__ __launch_bounds__(128) void flash_attn_kernel(float* __restrict__ out)
{
    __shared__ __align__(16) __half As[2 * ASTG];   // 36,864 B static
    __shared__ int s_job;

    const int tid = threadIdx.x, wid = tid >> 5, lane = tid & 31;
    const int gid = lane >> 2, tig = lane & 3;

    for (;;) {
        if (tid == 0) s_job = (int)atomicAdd(&g_job, 1u);
        __syncthreads();
        const int job = s_job;
        if (job >= NJOBS) return;

        const int b  = job & 7;
        const int qt = (T_ / 64 - 1) - (job >> 3);   // heavy jobs first
        const int m0 = qt * 64;
        const int rowbase = b * T_;

        auto issue_tile = [&](int nt, int st) {
            __half* Kh = As + st * ASTG;
            __half* Vh = Kh + ATS;
            const int n0 = nt * 64;
            #pragma unroll
            for (int i = 0; i < 4; i++) {
                int lin = tid + i * 128;
                int r = lin >> 3, cg = lin & 7;
                const size_t g = (size_t)(rowbase + n0 + r) * NC_;
                cp16(&Kh[r * KS_ + cg * 8], &g_hi[g + 64 + cg * 8]);
                cp16(&Vh[r * KS_ + cg * 8], &g_hi[g + 128 + cg * 8]);
            }
            cp_commit();
        };

        issue_tile(0, 0);

        // Q fragments (fp16, pre-scaled into exp2 domain), 4 k-chunks of 16.
        uint32_t qh[4][4];
        {
            const size_t r0 = (size_t)(rowbase + m0 + wid * 16 + gid) * NC_;
            #pragma unroll
            for (int kc = 0; kc < 4; kc++) {
                int c0 = kc * 16 + 2 * tig;
                qh[kc][0] = *(const uint32_t*)&g_hi[r0 + c0];
                qh[kc][1] = *(const uint32_t*)&g_hi[r0 + 8 * NC_ + c0];
                qh[kc][2] = *(const uint32_t*)&g_hi[r0 + c0 + 8];
                qh[kc][3] = *(const uint32_t*)&g_hi[r0 + 8 * NC_ + c0 + 8];
            }
        }

        float o[8][4];
        #pragma unroll
        for (int j = 0; j < 8; j++)
            #pragma unroll
            for (int c = 0; c < 4; c++) o[j][c] = 0.0f;
        float mrow0 = -INFINITY, mrow1 = -INFINITY, lrow0 = 0.0f, lrow1 = 0.0f;

        for (int nt = 0; nt <= qt; nt++) {
            const int n0 = nt * 64;
            const int p = nt & 1;
            __half* Kh = As + p * ASTG;
            __half* Vh = Kh + ATS;

            if (nt < qt) { issue_tile(nt + 1, p ^ 1); cp_wait<1>(); }
            else         { cp_wait<0>(); }
            __syncthreads();

            // S = qh * kh  (logits already in log2 domain).
            float s[8][4];
            #pragma unroll
            for (int j = 0; j < 8; j++)
                #pragma unroll
                for (int c = 0; c < 4; c++) s[j][c] = 0.0f;

            #pragma unroll
            for (int kc = 0; kc < 4; kc++) {
                #pragma unroll
                for (int j = 0; j < 8; j += 2) {
                    int key = 8 * j + (lane >> 4) * 8 + (lane & 7);
                    int c   = kc * 16 + ((lane >> 3) & 1) * 8;
                    uint32_t kh[4];
                    ldsm_x4(kh, su32(&Kh[key * KS_ + c]));
                    mma16816(s[j],     qh[kc], kh);
                    mma16816(s[j + 1], qh[kc], kh + 2);
                }
            }

            // Causal mask (diagonal tile only).
            if (nt == qt) {
                int r0 = m0 + wid * 16 + gid;
                #pragma unroll
                for (int j = 0; j < 8; j++) {
                    int c0 = n0 + 8 * j + 2 * tig;
                    if (c0     > r0)     s[j][0] = -INFINITY;
                    if (c0 + 1 > r0)     s[j][1] = -INFINITY;
                    if (c0     > r0 + 8) s[j][2] = -INFINITY;
                    if (c0 + 1 > r0 + 8) s[j][3] = -INFINITY;
                }
            }

            // Online softmax in exp2 domain (rows gid and gid+8).
            float mx0 = -INFINITY, mx1 = -INFINITY;
            #pragma unroll
            for (int j = 0; j < 8; j++) {
                mx0 = fmaxf(mx0, fmaxf(s[j][0], s[j][1]));
                mx1 = fmaxf(mx1, fmaxf(s[j][2], s[j][3]));
            }
            mx0 = fmaxf(mx0, __shfl_xor_sync(0xffffffffu, mx0, 1));
            mx0 = fmaxf(mx0, __shfl_xor_sync(0xffffffffu, mx0, 2));
            mx1 = fmaxf(mx1, __shfl_xor_sync(0xffffffffu, mx1, 1));
            mx1 = fmaxf(mx1, __shfl_xor_sync(0xffffffffu, mx1, 2));
            float mn0 = fmaxf(mrow0, mx0), mn1 = fmaxf(mrow1, mx1);
            float al0 = ex2(mrow0 - mn0), al1 = ex2(mrow1 - mn1);
            float rs0 = 0.0f, rs1 = 0.0f;
            #pragma unroll
            for (int j = 0; j < 8; j++) {
                s[j][0] = ex2(s[j][0] - mn0);
                s[j][1] = ex2(s[j][1] - mn0);
                s[j][2] = ex2(s[j][2] - mn1);
                s[j][3] = ex2(s[j][3] - mn1);
                rs0 += s[j][0] + s[j][1];
                rs1 += s[j][2] + s[j][3];
            }
            rs0 += __shfl_xor_sync(0xffffffffu, rs0, 1);
            rs0 += __shfl_xor_sync(0xffffffffu, rs0, 2);
            rs1 += __shfl_xor_sync(0xffffffffu, rs1, 1);
            rs1 += __shfl_xor_sync(0xffffffffu, rs1, 2);
            lrow0 = lrow0 * al0 + rs0;
            lrow1 = lrow1 * al1 + rs1;
            mrow0 = mn0; mrow1 = mn1;
            #pragma unroll
            for (int j = 0; j < 8; j++) {
                o[j][0] *= al0; o[j][1] *= al0;
                o[j][2] *= al1; o[j][3] *= al1;
            }

            // Pack P accumulator into fp16 A-fragments.
            uint32_t ph[4][4];
            #pragma unroll
            for (int kc = 0; kc < 4; kc++) {
                int j0 = 2 * kc, j1 = 2 * kc + 1;
                ph[kc][0] = pack2(s[j0][0], s[j0][1]);
                ph[kc][1] = pack2(s[j0][2], s[j0][3]);
                ph[kc][2] = pack2(s[j1][0], s[j1][1]);
                ph[kc][3] = pack2(s[j1][2], s[j1][3]);
            }

            // O += ph * vh.
            #pragma unroll
            for (int kc = 0; kc < 4; kc++) {
                #pragma unroll
                for (int j = 0; j < 8; j += 2) {
                    int key  = kc * 16 + (lane & 7) + ((lane & 8) ? 8 : 0);
                    int dcol = 8 * j + (lane >> 4) * 8;
                    uint32_t vh[4];
                    ldsm_x4t(vh, su32(&Vh[key * KS_ + dcol]));
                    mma16816(o[j],     ph[kc], vh);
                    mma16816(o[j + 1], ph[kc], vh + 2);
                }
            }
            __syncthreads();   // stage p reads done before nt+1 issues into it
        }

        // Epilogue: normalize, store fp32.
        float inv0 = 1.0f / lrow0, inv1 = 1.0f / lrow1;
        const int r0 = m0 + wid * 16 + gid;
        float* ob = out + (size_t)b * T_ * D_;
        #pragma unroll
        for (int j = 0; j < 8; j++) {
            int c = 8 * j + 2 * tig;
            *(float2*)&ob[(size_t)r0 * D_ + c] =
                make_float2(o[j][0] * inv0, o[j][1] * inv0);
            *(float2*)&ob[(size_t)(r0 + 8) * D_ + c] =
                make_float2(o[j][2] * inv1, o[j][3] * inv1);
        }

        __syncthreads();   // all reads of As/s_job complete before next job
    }
}

// ---------------------------------------------------------------------------
extern "C" void kernel_launch(void* const* d_in, const int* in_sizes, int n_in,
                              void* d_out, int out_size)
{
    const float* x  = (const float*)d_in[0];
    const float* Wq = (const float*)d_in[1];
    const float* bq = (const float*)d_in[2];
    const float* Wk = (const float*)d_in[3];
    const float* bk = (const float*)d_in[4];
    const float* Wv = (const float*)d_in[5];
    const float* bv = (const float*)d_in[6];
    float* out = (float*)d_out;

    wprep_kernel<<<(E_ * NC_ / 4 + 255) / 256, 256>>>(Wq, Wk, Wv);
    qkv_proj_kernel<<<BT_ / 64, 256>>>(x, bq, bk, bv);
    flash_attn_kernel<<<NCTAS, 128>>>(out);
}